// round 2
// baseline (speedup 1.0000x reference)
#include <cuda_runtime.h>
#include <math.h>

#define NN 100000
#define EE 1600000
#define NEG_INF __int_as_float(0xff800000)

// ---------------- device scratch (static allocation only) ----------------
__device__ float g_deg[NN];
__device__ float g_dinv[NN];
__device__ __align__(16) float g_aggx[NN * 64];   // A (without self term)
__device__ __align__(16) float g_hg[NN * 64];     // GAT h = A@W2 + B2
__device__ __align__(16) float g_g[NN * 64];      // GAT output accumulator
__device__ float g_h1[NN * 128];                  // MLP hidden
__device__ float g_S[NN * 80];                    // MHA logits
__device__ float g_ssrc[NN], g_sdst[NN];
__device__ float g_m[NN], g_den[NN];
__device__ float g_logit[EE];
__device__ float g_U2[80 * 64], g_C2[80];
__device__ float g_W2[64 * 64], g_B2[64];
__device__ float g_M[80], g_Dacc[80], g_Znum[80 * 64];
__device__ __align__(16) float g_avec[64];

// ---------------- helpers ----------------
__device__ __forceinline__ void atomicMaxF(float* a, float v) {
    if (v >= 0.f) atomicMax((int*)a, __float_as_int(v));
    else          atomicMin((unsigned int*)a, __float_as_uint(v));
}

__device__ __forceinline__ void redAdd4(float4* p, float4 v) {
    asm volatile("red.global.add.v4.f32 [%0], {%1,%2,%3,%4};"
                 :: "l"(p), "f"(v.x), "f"(v.y), "f"(v.z), "f"(v.w) : "memory");
}

// ---------------- init ----------------
__global__ void k_init(const float* __restrict__ gat_b) {
    int idx = blockIdx.x * 256 + threadIdx.x;           // covers NN*64 exactly
    g_aggx[idx] = 0.f;
    g_g[idx]    = gat_b[idx & 63];
    if (idx < NN) { g_deg[idx] = 1.f; g_m[idx] = NEG_INF; g_den[idx] = 0.f; }
    if (idx < 80) { g_M[idx] = NEG_INF; g_Dacc[idx] = 0.f; }
    if (idx < 80 * 64) g_Znum[idx] = 0.f;
}

// ---------------- degree / dinv ----------------
__global__ void k_deg(const int* __restrict__ ei) {
    int e = blockIdx.x * 256 + threadIdx.x;             // EE exactly
    atomicAdd(&g_deg[ei[EE + e]], 1.f);
}

__global__ void k_dinv() {
    int n = blockIdx.x * 256 + threadIdx.x;
    if (n < NN) g_dinv[n] = rsqrtf(g_deg[n]);
}

// ---------------- GCN edge aggregation (shared by K/V via linearity) ----------------
__global__ void k_gcn_edge(const int* __restrict__ ei, const float* __restrict__ x) {
    int idx = blockIdx.x * 256 + threadIdx.x;           // EE*16 exactly
    int e = idx >> 4, q = idx & 15;
    int s = ei[e], d = ei[EE + e];
    float w = g_dinv[s] * g_dinv[d];
    float4 v = ((const float4*)x)[s * 16 + q];
    v.x *= w; v.y *= w; v.z *= w; v.w *= w;
    redAdd4(&((float4*)g_aggx)[d * 16 + q], v);
}

// ---------------- small kernel 1: fold all tiny matrices ----------------
__global__ void k_small1(const float* __restrict__ superQ,
                         const float* __restrict__ in_w, const float* __restrict__ in_b,
                         const float* __restrict__ gcnK_W, const float* __restrict__ gcnK_b,
                         const float* __restrict__ gcnV_W, const float* __restrict__ gcnV_b,
                         const float* __restrict__ gat_W) {
    __shared__ float s_qh[640];
    __shared__ float s_u[5120];
    __shared__ float s_c0[80];
    int t = threadIdx.x;
    const float scale = 0.35355339059327373f;  // 1/sqrt(8)
    for (int i = t; i < 640; i += 256) {
        int l = i >> 6, ii = i & 63;
        float acc = in_b[ii];
        for (int k = 0; k < 64; k++) acc += superQ[l * 64 + k] * in_w[ii * 64 + k];
        s_qh[i] = acc * scale;
    }
    __syncthreads();
    for (int i = t; i < 5120; i += 256) {
        int c = i >> 6, k = i & 63;
        int h = c / 10, l = c % 10;
        float acc = 0.f;
        for (int j = 0; j < 8; j++)
            acc += s_qh[l * 64 + h * 8 + j] * in_w[(64 + h * 8 + j) * 64 + k];
        s_u[i] = acc;
    }
    if (t < 80) {
        int h = t / 10, l = t % 10;
        float acc = 0.f;
        for (int j = 0; j < 8; j++) acc += s_qh[l * 64 + h * 8 + j] * in_b[64 + h * 8 + j];
        s_c0[t] = acc;
    }
    __syncthreads();
    // u2 = gcnK_W @ u ; c2 = c0 + bK.u
    for (int i = t; i < 5120; i += 256) {
        int c = i >> 6, kp = i & 63;
        float acc = 0.f;
        for (int k = 0; k < 64; k++) acc += gcnK_W[kp * 64 + k] * s_u[c * 64 + k];
        g_U2[i] = acc;
    }
    if (t < 80) {
        float acc = s_c0[t];
        for (int k = 0; k < 64; k++) acc += gcnK_b[k] * s_u[t * 64 + k];
        g_C2[t] = acc;
    }
    // W2 = gcnV_W @ gat_W ; B2 = gcnV_b @ gat_W
    for (int i = t; i < 4096; i += 256) {
        int kp = i >> 6, j = i & 63;
        float acc = 0.f;
        for (int k = 0; k < 64; k++) acc += gcnV_W[kp * 64 + k] * gat_W[k * 64 + j];
        g_W2[i] = acc;
    }
    if (t < 64) {
        float acc = 0.f;
        for (int k = 0; k < 64; k++) acc += gcnV_b[k] * gat_W[k * 64 + t];
        g_B2[t] = acc;
    }
}

// ---------------- hg = A @ W2 + B2 ----------------
__global__ void k_hg(const float* __restrict__ x) {
    __shared__ float sW[64 * 64];
    __shared__ float sA[32 * 65];
    int t = threadIdx.x, n0 = blockIdx.x * 32;
    for (int i = t; i < 4096; i += 256) sW[i] = g_W2[i];
#pragma unroll
    for (int i = 0; i < 8; i++) {
        int lin = t + 256 * i, r = lin >> 6, k = lin & 63, n = n0 + r;
        float di = g_dinv[n];
        sA[r * 65 + k] = g_aggx[n * 64 + k] + x[n * 64 + k] * di * di;
    }
    __syncthreads();
    int r = t >> 3, cb = (t & 7) * 8;
    float acc[8];
#pragma unroll
    for (int j = 0; j < 8; j++) acc[j] = g_B2[cb + j];
    for (int k = 0; k < 64; k++) {
        float a = sA[r * 65 + k];
#pragma unroll
        for (int j = 0; j < 8; j++) acc[j] += a * sW[k * 64 + cb + j];
    }
    int n = n0 + r;
#pragma unroll
    for (int j = 0; j < 8; j++) g_hg[n * 64 + cb + j] = acc[j];
}

// ---------------- MHA pass 1: S = A@U2^T + c2, global max ----------------
__global__ void k_pass1(const float* __restrict__ x) {
    __shared__ float sU[80 * 65];
    __shared__ float sC[80];
    __shared__ float sA[32 * 65];
    __shared__ float sMax[80];
    int t = threadIdx.x, n0 = blockIdx.x * 32;
    for (int i = t; i < 5120; i += 256) { int c = i >> 6, k = i & 63; sU[c * 65 + k] = g_U2[i]; }
    if (t < 80) { sC[t] = g_C2[t]; sMax[t] = NEG_INF; }
#pragma unroll
    for (int i = 0; i < 8; i++) {
        int lin = t + 256 * i, r = lin >> 6, k = lin & 63, n = n0 + r;
        float di = g_dinv[n];
        sA[r * 65 + k] = g_aggx[n * 64 + k] + x[n * 64 + k] * di * di;
    }
    __syncthreads();
    int r = t >> 3, cg = t & 7;
    float acc[10];
#pragma unroll
    for (int i = 0; i < 10; i++) acc[i] = sC[cg * 10 + i];
    for (int k = 0; k < 64; k++) {
        float a = sA[r * 65 + k];
#pragma unroll
        for (int i = 0; i < 10; i++) acc[i] += a * sU[(cg * 10 + i) * 65 + k];
    }
    int n = n0 + r;
#pragma unroll
    for (int i = 0; i < 10; i++) {
        g_S[n * 80 + cg * 10 + i] = acc[i];
        atomicMaxF(&sMax[cg * 10 + i], acc[i]);
    }
    __syncthreads();
    if (t < 80) atomicMaxF(&g_M[t], sMax[t]);
}

// ---------------- MHA pass 2: Znum = E^T A, Dacc = colsum(E) ----------------
__global__ void k_pass2(const float* __restrict__ x) {
    __shared__ float sE[64 * 80];
    __shared__ float sA[64 * 65];
    __shared__ float sM[80];
    int t = threadIdx.x, n0 = blockIdx.x * 64;
    if (t < 80) sM[t] = g_M[t];
    __syncthreads();
#pragma unroll
    for (int i = 0; i < 20; i++) {
        int lin = t + 256 * i, r = lin / 80, c = lin % 80, n = n0 + r;
        sE[lin] = (n < NN) ? __expf(g_S[n * 80 + c] - sM[c]) : 0.f;
    }
#pragma unroll
    for (int i = 0; i < 16; i++) {
        int lin = t + 256 * i, r = lin >> 6, k = lin & 63, n = n0 + r;
        float v = 0.f;
        if (n < NN) { float di = g_dinv[n]; v = g_aggx[n * 64 + k] + x[n * 64 + k] * di * di; }
        sA[r * 65 + k] = v;
    }
    __syncthreads();
    int k = t & 63, cg = t >> 6;
    float acc[20];
#pragma unroll
    for (int i = 0; i < 20; i++) acc[i] = 0.f;
    for (int r = 0; r < 64; r++) {
        float a = sA[r * 65 + k];
#pragma unroll
        for (int i = 0; i < 20; i++) acc[i] += sE[r * 80 + cg * 20 + i] * a;
    }
#pragma unroll
    for (int i = 0; i < 20; i++) atomicAdd(&g_Znum[(cg * 20 + i) * 64 + k], acc[i]);
    if (t < 80) {
        float s = 0.f;
        for (int r = 0; r < 64; r++) s += sE[r * 80 + t];
        atomicAdd(&g_Dacc[t], s);
    }
}

// ---------------- small kernel 2: cluster, context, avec ----------------
__global__ void k_small2(const float* __restrict__ in_w, const float* __restrict__ in_b,
                         const float* __restrict__ out_w, const float* __restrict__ out_b,
                         const float* __restrict__ gcnV_W, const float* __restrict__ gcnV_b,
                         const float* __restrict__ gat_Wc, const float* __restrict__ a_src) {
    __shared__ float s_zA[5120];
    __shared__ float s_zV[5120];
    __shared__ float s_o[640];
    __shared__ float s_mo[64];
    __shared__ float s_ctx[64];
    int t = threadIdx.x;  // 128
    for (int i = t; i < 5120; i += 128) s_zA[i] = g_Znum[i] / g_Dacc[i >> 6];
    __syncthreads();
    for (int i = t; i < 5120; i += 128) {
        int c = i >> 6, k = i & 63;
        float acc = gcnV_b[k];
        for (int kp = 0; kp < 64; kp++) acc += s_zA[c * 64 + kp] * gcnV_W[kp * 64 + k];
        s_zV[i] = acc;
    }
    __syncthreads();
    for (int i = t; i < 640; i += 128) {
        int l = i >> 6, ii = i & 63;
        int c = (ii >> 3) * 10 + l;
        float acc = in_b[128 + ii];
        for (int k = 0; k < 64; k++) acc += s_zV[c * 64 + k] * in_w[(128 + ii) * 64 + k];
        s_o[i] = acc;
    }
    __syncthreads();
    if (t < 64) {
        float acc = 0.f;
        for (int l = 0; l < 10; l++) acc += s_o[l * 64 + t];
        s_mo[t] = acc * 0.1f;
    }
    __syncthreads();
    if (t < 64) {
        float acc = out_b[t];
        for (int i = 0; i < 64; i++) acc += s_mo[i] * out_w[t * 64 + i];
        s_ctx[t] = acc;
    }
    __syncthreads();
    if (t < 64) {
        float acc = a_src[t];
        for (int kp = 0; kp < 64; kp++) acc += s_ctx[kp] * gat_Wc[kp * 64 + t];
        g_avec[t] = acc;
    }
}

// ---------------- GAT node scores ----------------
__global__ void k_sdots(const float* __restrict__ a_dst) {
    int w = blockIdx.x * 8 + (threadIdx.x >> 5);
    int lane = threadIdx.x & 31;
    if (w >= NN) return;
    float2 h  = ((const float2*)g_hg)[w * 32 + lane];
    float2 av = ((const float2*)g_avec)[lane];
    float2 ad = ((const float2*)a_dst)[lane];
    float p1 = h.x * av.x + h.y * av.y;
    float p2 = h.x * ad.x + h.y * ad.y;
#pragma unroll
    for (int off = 16; off; off >>= 1) {
        p1 += __shfl_down_sync(0xffffffffu, p1, off);
        p2 += __shfl_down_sync(0xffffffffu, p2, off);
    }
    if (lane == 0) { g_ssrc[w] = p1; g_sdst[w] = p2; }
}

// ---------------- GAT edge passes ----------------
__global__ void k_gat1(const int* __restrict__ ei) {
    int e = blockIdx.x * 256 + threadIdx.x;
    int s = ei[e], d = ei[EE + e];
    float v = g_ssrc[s] + g_sdst[d];
    v = (v >= 0.f) ? v : 0.2f * v;
    g_logit[e] = v;
    atomicMaxF(&g_m[d], v);
}

__global__ void k_gat2(const int* __restrict__ ei) {
    int e = blockIdx.x * 256 + threadIdx.x;
    int d = ei[EE + e];
    float ex = __expf(g_logit[e] - g_m[d]);
    g_logit[e] = ex;
    atomicAdd(&g_den[d], ex);
}

__global__ void k_rden() {
    int n = blockIdx.x * 256 + threadIdx.x;
    if (n < NN) g_den[n] = 1.f / (g_den[n] + 1e-16f);
}

__global__ void k_gat3(const int* __restrict__ ei) {
    int idx = blockIdx.x * 256 + threadIdx.x;   // EE*16
    int e = idx >> 4, q = idx & 15;
    int s = ei[e], d = ei[EE + e];
    float alpha = g_logit[e] * g_den[d];
    float4 v = ((const float4*)g_hg)[s * 16 + q];
    v.x *= alpha; v.y *= alpha; v.z *= alpha; v.w *= alpha;
    redAdd4(&((float4*)g_g)[d * 16 + q], v);
}

// ---------------- MLP ----------------
__global__ void k_mlp1(const float* __restrict__ t1_W, const float* __restrict__ t1_b) {
    __shared__ float sW[64 * 128];
    __shared__ float sG[32 * 65];
    int t = threadIdx.x, n0 = blockIdx.x * 32;
    for (int i = t; i < 8192; i += 256) sW[i] = t1_W[i];
#pragma unroll
    for (int i = 0; i < 8; i++) {
        int lin = t + 256 * i, r = lin >> 6, k = lin & 63;
        sG[r * 65 + k] = g_g[(n0 + r) * 64 + k];
    }
    __syncthreads();
    int r = t >> 3, mg = (t & 7) * 16;
    float acc[16];
#pragma unroll
    for (int i = 0; i < 16; i++) acc[i] = t1_b[mg + i];
    for (int k = 0; k < 64; k++) {
        float gv = sG[r * 65 + k];
#pragma unroll
        for (int i = 0; i < 16; i++) acc[i] += gv * sW[k * 128 + mg + i];
    }
    int n = n0 + r;
#pragma unroll
    for (int i = 0; i < 16; i++) g_h1[n * 128 + mg + i] = fmaxf(acc[i], 0.f);
}

__global__ void k_mlp2(const float* __restrict__ t2_W, const float* __restrict__ t2_b,
                       float* __restrict__ out) {
    __shared__ float sW[128 * 64];
    __shared__ float sH[16 * 132];
    int t = threadIdx.x, n0 = blockIdx.x * 16;
    for (int i = t; i < 8192; i += 256) sW[i] = t2_W[i];
#pragma unroll
    for (int i = 0; i < 8; i++) {
        int lin = t + 256 * i, r = lin >> 7, m = lin & 127;
        sH[r * 132 + m] = g_h1[(n0 + r) * 128 + m];
    }
    __syncthreads();
    int r = t >> 4, cb = (t & 15) * 4;
    float acc[4];
#pragma unroll
    for (int i = 0; i < 4; i++) acc[i] = t2_b[cb + i];
    for (int m = 0; m < 128; m++) {
        float hv = sH[r * 132 + m];
#pragma unroll
        for (int i = 0; i < 4; i++) acc[i] += hv * sW[m * 64 + cb + i];
    }
    int n = n0 + r;
#pragma unroll
    for (int i = 0; i < 4; i++) out[n * 64 + cb + i] = fmaxf(acc[i], 0.f);
}

// ---------------- launch ----------------
extern "C" void kernel_launch(void* const* d_in, const int* in_sizes, int n_in,
                              void* d_out, int out_size) {
    const float* x        = (const float*)d_in[0];
    const int*   ei       = (const int*)d_in[1];
    const float* gcnK_W   = (const float*)d_in[2];
    const float* gcnK_b   = (const float*)d_in[3];
    const float* gcnV_W   = (const float*)d_in[4];
    const float* gcnV_b   = (const float*)d_in[5];
    const float* super_Q  = (const float*)d_in[6];
    const float* mha_in_w = (const float*)d_in[7];
    const float* mha_in_b = (const float*)d_in[8];
    const float* mha_out_w= (const float*)d_in[9];
    const float* mha_out_b= (const float*)d_in[10];
    const float* gat_W    = (const float*)d_in[11];
    const float* gat_Wc   = (const float*)d_in[12];
    const float* gat_a_src= (const float*)d_in[13];
    const float* gat_a_dst= (const float*)d_in[14];
    const float* gat_b    = (const float*)d_in[15];
    const float* t1_W     = (const float*)d_in[16];
    const float* t1_b     = (const float*)d_in[17];
    const float* t2_W     = (const float*)d_in[18];
    const float* t2_b     = (const float*)d_in[19];
    float* out = (float*)d_out;

    k_init<<<25000, 256>>>(gat_b);                         // NN*64
    k_deg<<<6250, 256>>>(ei);                              // EE
    k_dinv<<<391, 256>>>();
    k_gcn_edge<<<100000, 256>>>(ei, x);                    // EE*16
    k_small1<<<1, 256>>>(super_Q, mha_in_w, mha_in_b, gcnK_W, gcnK_b,
                         gcnV_W, gcnV_b, gat_W);
    k_hg<<<3125, 256>>>(x);
    k_pass1<<<3125, 256>>>(x);
    k_pass2<<<1563, 256>>>(x);
    k_small2<<<1, 128>>>(mha_in_w, mha_in_b, mha_out_w, mha_out_b,
                         gcnV_W, gcnV_b, gat_Wc, gat_a_src);
    k_sdots<<<12500, 256>>>(gat_a_dst);
    k_gat1<<<6250, 256>>>(ei);
    k_gat2<<<6250, 256>>>(ei);
    k_rden<<<391, 256>>>();
    k_gat3<<<100000, 256>>>(ei);                           // EE*16
    k_mlp1<<<3125, 256>>>(t1_W, t1_b);
    k_mlp2<<<6250, 256>>>(t2_W, t2_b, out);
}

// round 5
// speedup vs baseline: 1.5206x; 1.5206x over previous
#include <cuda_runtime.h>
#include <math.h>

#define NN 100000
#define EE 1600000

// ---------------- device scratch ----------------
__device__ float g_deg[NN];
__device__ float g_dinv[NN];
__device__ __align__(16) float g_aggx[NN * 64];   // edge-aggregated x (no self term)
__device__ __align__(16) float g_hg[NN * 64];     // GAT h = A@W2 + B2
__device__ __align__(16) float g_g[NN * 64];      // GAT output accumulator
__device__ float g_ssrc[NN], g_sdst[NN];
__device__ float g_den[NN];
__device__ float g_logit[EE];
__device__ float g_U2[80 * 64], g_C2[80];
__device__ float g_W2[64 * 64], g_B2[64];
__device__ float g_Dacc[80];
__device__ __align__(16) float g_Znum[80 * 64];
__device__ __align__(16) float g_avec[64];

__device__ __forceinline__ void redAdd4(float4* p, float4 v) {
    asm volatile("red.global.add.v4.f32 [%0], {%1,%2,%3,%4};"
                 :: "l"(p), "f"(v.x), "f"(v.y), "f"(v.z), "f"(v.w) : "memory");
}

// ---------------- init ----------------
__global__ void k_init(const float* __restrict__ gat_b) {
    int idx = blockIdx.x * 256 + threadIdx.x;           // NN*64 exactly
    g_aggx[idx] = 0.f;
    g_g[idx]    = gat_b[idx & 63];
    if (idx < NN) { g_deg[idx] = 1.f; g_den[idx] = 0.f; }
    if (idx < 80 * 64) g_Znum[idx] = 0.f;
    if (idx < 80) g_Dacc[idx] = 0.f;
}

// ---------------- degree / dinv ----------------
__global__ void k_deg(const int* __restrict__ ei) {
    int e = blockIdx.x * 256 + threadIdx.x;             // EE exactly
    atomicAdd(&g_deg[ei[EE + e]], 1.f);
}

__global__ void k_dinv() {
    int n = blockIdx.x * 256 + threadIdx.x;
    if (n < NN) g_dinv[n] = rsqrtf(g_deg[n]);
}

// ---------------- GCN edge aggregation ----------------
__global__ void k_gcn_edge(const int* __restrict__ ei, const float* __restrict__ x) {
    int idx = blockIdx.x * 256 + threadIdx.x;           // EE*16 exactly
    int e = idx >> 4, q = idx & 15;
    int s = ei[e], d = ei[EE + e];
    float w = g_dinv[s] * g_dinv[d];
    float4 v = ((const float4*)x)[s * 16 + q];
    v.x *= w; v.y *= w; v.z *= w; v.w *= w;
    redAdd4(&((float4*)g_aggx)[d * 16 + q], v);
}

// ---------------- small kernel 1: fold tiny matrices ----------------
__global__ void k_small1(const float* __restrict__ superQ,
                         const float* __restrict__ in_w, const float* __restrict__ in_b,
                         const float* __restrict__ gcnK_W, const float* __restrict__ gcnK_b,
                         const float* __restrict__ gcnV_W, const float* __restrict__ gcnV_b,
                         const float* __restrict__ gat_W) {
    __shared__ float s_qh[640];
    __shared__ float s_u[5120];
    __shared__ float s_c0[80];
    int t = threadIdx.x;
    const float scale = 0.35355339059327373f;  // 1/sqrt(8)
    for (int i = t; i < 640; i += 256) {
        int l = i >> 6, ii = i & 63;
        float acc = in_b[ii];
        for (int k = 0; k < 64; k++) acc += superQ[l * 64 + k] * in_w[ii * 64 + k];
        s_qh[i] = acc * scale;
    }
    __syncthreads();
    for (int i = t; i < 5120; i += 256) {
        int c = i >> 6, k = i & 63;
        int h = c / 10, l = c % 10;
        float acc = 0.f;
        for (int j = 0; j < 8; j++)
            acc += s_qh[l * 64 + h * 8 + j] * in_w[(64 + h * 8 + j) * 64 + k];
        s_u[i] = acc;
    }
    if (t < 80) {
        int h = t / 10, l = t % 10;
        float acc = 0.f;
        for (int j = 0; j < 8; j++) acc += s_qh[l * 64 + h * 8 + j] * in_b[64 + h * 8 + j];
        s_c0[t] = acc;
    }
    __syncthreads();
    for (int i = t; i < 5120; i += 256) {
        int c = i >> 6, kp = i & 63;
        float acc = 0.f;
        for (int k = 0; k < 64; k++) acc += gcnK_W[kp * 64 + k] * s_u[c * 64 + k];
        g_U2[i] = acc;
    }
    if (t < 80) {
        float acc = s_c0[t];
        for (int k = 0; k < 64; k++) acc += gcnK_b[k] * s_u[t * 64 + k];
        g_C2[t] = acc;
    }
    for (int i = t; i < 4096; i += 256) {
        int kp = i >> 6, j = i & 63;
        float acc = 0.f;
        for (int k = 0; k < 64; k++) acc += gcnV_W[kp * 64 + k] * gat_W[k * 64 + j];
        g_W2[i] = acc;
    }
    if (t < 64) {
        float acc = 0.f;
        for (int k = 0; k < 64; k++) acc += gcnV_b[k] * gat_W[k * 64 + t];
        g_B2[t] = acc;
    }
}

// ---------------- fused node pass: hg GEMM + MHA S/exp + Znum/Dacc ----------------
// 80 rows per block, grid = 1250 (exact). Dynamic smem.
#define SA_STR 68
#define SE_STR 84
#define NODEA_SMEM ((80*SA_STR + 80*SA_STR + 64*64 + 80*SE_STR + 80 + 64 + 80) * 4)
__global__ void __launch_bounds__(256) k_nodeA(const float* __restrict__ x) {
    extern __shared__ float sm[];
    float* sA    = sm;                       // [80][68]
    float* sU    = sA + 80 * SA_STR;         // [80][68]  U2[c][k]
    float* sW    = sU + 80 * SA_STR;         // [64][64]  W2[k][j]
    float* sE    = sW + 64 * 64;             // [80][84]
    float* sC    = sE + 80 * SE_STR;         // [80]
    float* sB2   = sC + 80;                  // [64]
    float* sDinv = sB2 + 64;                 // [80]

    int t = threadIdx.x;
    int n0 = blockIdx.x * 80;

    for (int i = t; i < 4096; i += 256) sW[i] = g_W2[i];
    for (int i = t; i < 5120; i += 256) { int c = i >> 6, k = i & 63; sU[c * SA_STR + k] = g_U2[i]; }
    if (t < 80) { sC[t] = g_C2[t]; sDinv[t] = g_dinv[n0 + t]; }
    if (t < 64) sB2[t] = g_B2[t];
    __syncthreads();

    // load A = aggx + x*dinv^2  (80 rows x 16 float4)
#pragma unroll
    for (int i = 0; i < 5; i++) {
        int idx = t + 256 * i, r = idx >> 4, q = idx & 15;
        int n = n0 + r;
        float di = sDinv[r], d2 = di * di;
        float4 a  = ((const float4*)g_aggx)[n * 16 + q];
        float4 xv = ((const float4*)x)[n * 16 + q];
        a.x += xv.x * d2; a.y += xv.y * d2; a.z += xv.z * d2; a.w += xv.w * d2;
        *(float4*)&sA[r * SA_STR + q * 4] = a;
    }
    __syncthreads();

    // ---- phase hg: 5 rows x 4 cols per thread ----
    {
        int rq = t >> 4, cg = t & 15;           // rows rq*5.., cols cg*4..
        float4 acc[5];
        float4 b = *(float4*)&sB2[cg * 4];
#pragma unroll
        for (int i = 0; i < 5; i++) acc[i] = b;
        for (int k = 0; k < 64; k++) {
            float4 w = *(float4*)&sW[k * 64 + cg * 4];
#pragma unroll
            for (int i = 0; i < 5; i++) {
                float a = sA[(rq * 5 + i) * SA_STR + k];
                acc[i].x += a * w.x; acc[i].y += a * w.y;
                acc[i].z += a * w.z; acc[i].w += a * w.w;
            }
        }
#pragma unroll
        for (int i = 0; i < 5; i++)
            *(float4*)&g_hg[(n0 + rq * 5 + i) * 64 + cg * 4] = acc[i];
    }

    // ---- phase S/E: 5 rows x 5 cols per thread, exp in place ----
    {
        int rq = t >> 4, cgrp = t & 15;         // rows rq*5.., cols cgrp*5..
        float acc[5][5];
#pragma unroll
        for (int j = 0; j < 5; j++) {
            float c0 = sC[cgrp * 5 + j];
#pragma unroll
            for (int i = 0; i < 5; i++) acc[i][j] = c0;
        }
        for (int k = 0; k < 64; k++) {
            float a[5], u[5];
#pragma unroll
            for (int i = 0; i < 5; i++) a[i] = sA[(rq * 5 + i) * SA_STR + k];
#pragma unroll
            for (int j = 0; j < 5; j++) u[j] = sU[(cgrp * 5 + j) * SA_STR + k];
#pragma unroll
            for (int i = 0; i < 5; i++)
#pragma unroll
                for (int j = 0; j < 5; j++) acc[i][j] += a[i] * u[j];
        }
#pragma unroll
        for (int i = 0; i < 5; i++)
#pragma unroll
            for (int j = 0; j < 5; j++)
                sE[(rq * 5 + i) * SE_STR + cgrp * 5 + j] = __expf(acc[i][j]);
    }
    __syncthreads();

    // ---- phase Znum: 5 cols x 4 k per thread ----
    {
        int cq = t >> 4, kg = t & 15;           // c = cq*5.., k = kg*4..
        float4 z[5];
#pragma unroll
        for (int j = 0; j < 5; j++) z[j] = make_float4(0.f, 0.f, 0.f, 0.f);
        for (int r = 0; r < 80; r++) {
            float4 a = *(float4*)&sA[r * SA_STR + kg * 4];
#pragma unroll
            for (int j = 0; j < 5; j++) {
                float e = sE[r * SE_STR + cq * 5 + j];
                z[j].x += e * a.x; z[j].y += e * a.y;
                z[j].z += e * a.z; z[j].w += e * a.w;
            }
        }
#pragma unroll
        for (int j = 0; j < 5; j++)
            redAdd4((float4*)&g_Znum[(cq * 5 + j) * 64 + kg * 4], z[j]);
    }
    if (t < 80) {
        float s = 0.f;
        for (int r = 0; r < 80; r++) s += sE[r * SE_STR + t];
        atomicAdd(&g_Dacc[t], s);
    }
}

// ---------------- small kernel 2: cluster, context, avec ----------------
__global__ void k_small2(const float* __restrict__ in_w, const float* __restrict__ in_b,
                         const float* __restrict__ out_w, const float* __restrict__ out_b,
                         const float* __restrict__ gcnV_W, const float* __restrict__ gcnV_b,
                         const float* __restrict__ gat_Wc, const float* __restrict__ a_src) {
    __shared__ float s_zA[5120];
    __shared__ float s_zV[5120];
    __shared__ float s_o[640];
    __shared__ float s_mo[64];
    __shared__ float s_ctx[64];
    int t = threadIdx.x;  // 128
    for (int i = t; i < 5120; i += 128) s_zA[i] = g_Znum[i] / g_Dacc[i >> 6];
    __syncthreads();
    for (int i = t; i < 5120; i += 128) {
        int c = i >> 6, k = i & 63;
        float acc = gcnV_b[k];
        for (int kp = 0; kp < 64; kp++) acc += s_zA[c * 64 + kp] * gcnV_W[kp * 64 + k];
        s_zV[i] = acc;
    }
    __syncthreads();
    for (int i = t; i < 640; i += 128) {
        int l = i >> 6, ii = i & 63;
        int c = (ii >> 3) * 10 + l;
        float acc = in_b[128 + ii];
        for (int k = 0; k < 64; k++) acc += s_zV[c * 64 + k] * in_w[(128 + ii) * 64 + k];
        s_o[i] = acc;
    }
    __syncthreads();
    if (t < 64) {
        float acc = 0.f;
        for (int l = 0; l < 10; l++) acc += s_o[l * 64 + t];
        s_mo[t] = acc * 0.1f;
    }
    __syncthreads();
    if (t < 64) {
        float acc = out_b[t];
        for (int i = 0; i < 64; i++) acc += s_mo[i] * out_w[t * 64 + i];
        s_ctx[t] = acc;
    }
    __syncthreads();
    if (t < 64) {
        float acc = a_src[t];
        for (int kp = 0; kp < 64; kp++) acc += s_ctx[kp] * gat_Wc[kp * 64 + t];
        g_avec[t] = acc;
    }
}

// ---------------- GAT node scores ----------------
__global__ void k_sdots(const float* __restrict__ a_dst) {
    int w = blockIdx.x * 8 + (threadIdx.x >> 5);
    int lane = threadIdx.x & 31;
    if (w >= NN) return;
    float2 h  = ((const float2*)g_hg)[w * 32 + lane];
    float2 av = ((const float2*)g_avec)[lane];
    float2 ad = ((const float2*)a_dst)[lane];
    float p1 = h.x * av.x + h.y * av.y;
    float p2 = h.x * ad.x + h.y * ad.y;
#pragma unroll
    for (int off = 16; off; off >>= 1) {
        p1 += __shfl_down_sync(0xffffffffu, p1, off);
        p2 += __shfl_down_sync(0xffffffffu, p2, off);
    }
    if (lane == 0) { g_ssrc[w] = p1; g_sdst[w] = p2; }
}

// ---------------- GAT edge passes (no max pass: logits are O(1)) ----------------
__global__ void k_gatE(const int* __restrict__ ei) {
    int e = blockIdx.x * 256 + threadIdx.x;
    int s = ei[e], d = ei[EE + e];
    float v = g_ssrc[s] + g_sdst[d];
    v = (v >= 0.f) ? v : 0.2f * v;
    float ex = __expf(v);
    g_logit[e] = ex;
    atomicAdd(&g_den[d], ex);
}

__global__ void k_rden() {
    int n = blockIdx.x * 256 + threadIdx.x;
    if (n < NN) g_den[n] = 1.f / (g_den[n] + 1e-16f);
}

__global__ void k_gat3(const int* __restrict__ ei) {
    int idx = blockIdx.x * 256 + threadIdx.x;   // EE*16
    int e = idx >> 4, q = idx & 15;
    int s = ei[e], d = ei[EE + e];
    float alpha = g_logit[e] * g_den[d];
    float4 v = ((const float4*)g_hg)[s * 16 + q];
    v.x *= alpha; v.y *= alpha; v.z *= alpha; v.w *= alpha;
    redAdd4(&((float4*)g_g)[d * 16 + q], v);
}

// ---------------- fused MLP: out = relu(relu(g@W1+b1)@W2+b2) ----------------
// 32 rows per block, grid 3125 (exact). Dynamic smem.
#define SG_STR 68
#define SH_STR 132
#define MLP_SMEM ((64*128 + 128*64 + 32*SG_STR + 32*SH_STR + 128 + 64) * 4)
__global__ void __launch_bounds__(256) k_mlp(const float* __restrict__ t1_W, const float* __restrict__ t1_b,
                                             const float* __restrict__ t2_W, const float* __restrict__ t2_b,
                                             float* __restrict__ out) {
    extern __shared__ float sm[];
    float* sW1 = sm;                  // [64][128]
    float* sW2 = sW1 + 64 * 128;      // [128][64]
    float* sG  = sW2 + 128 * 64;      // [32][68]
    float* sH  = sG + 32 * SG_STR;    // [32][132]
    float* sB1 = sH + 32 * SH_STR;    // [128]
    float* sB2 = sB1 + 128;           // [64]

    int t = threadIdx.x;
    int n0 = blockIdx.x * 32;

    for (int i = t; i < 8192; i += 256) { sW1[i] = t1_W[i]; sW2[i] = t2_W[i]; }
    if (t < 128) sB1[t] = t1_b[t];
    if (t < 64) sB2[t] = t2_b[t];
#pragma unroll
    for (int i = 0; i < 2; i++) {
        int idx = t + 256 * i, r = idx >> 4, q = idx & 15;
        *(float4*)&sG[r * SG_STR + q * 4] = ((const float4*)g_g)[(n0 + r) * 16 + q];
    }
    __syncthreads();

    // phase 1: h = relu(g@W1 + b1): 2 rows x 8 cols per thread
    {
        int rq = t >> 4, cg = t & 15;        // rows rq*2.., cols cg*8..
        float4 acc[2][2];
        float4 b0 = *(float4*)&sB1[cg * 8];
        float4 b1v = *(float4*)&sB1[cg * 8 + 4];
        acc[0][0] = b0; acc[0][1] = b1v; acc[1][0] = b0; acc[1][1] = b1v;
        for (int k = 0; k < 64; k++) {
            float4 w0 = *(float4*)&sW1[k * 128 + cg * 8];
            float4 w1 = *(float4*)&sW1[k * 128 + cg * 8 + 4];
            float a0 = sG[(rq * 2) * SG_STR + k];
            float a1 = sG[(rq * 2 + 1) * SG_STR + k];
            acc[0][0].x += a0 * w0.x; acc[0][0].y += a0 * w0.y; acc[0][0].z += a0 * w0.z; acc[0][0].w += a0 * w0.w;
            acc[0][1].x += a0 * w1.x; acc[0][1].y += a0 * w1.y; acc[0][1].z += a0 * w1.z; acc[0][1].w += a0 * w1.w;
            acc[1][0].x += a1 * w0.x; acc[1][0].y += a1 * w0.y; acc[1][0].z += a1 * w0.z; acc[1][0].w += a1 * w0.w;
            acc[1][1].x += a1 * w1.x; acc[1][1].y += a1 * w1.y; acc[1][1].z += a1 * w1.z; acc[1][1].w += a1 * w1.w;
        }
#pragma unroll
        for (int i = 0; i < 2; i++)
#pragma unroll
            for (int j = 0; j < 2; j++) {
                float4 v = acc[i][j];
                v.x = fmaxf(v.x, 0.f); v.y = fmaxf(v.y, 0.f);
                v.z = fmaxf(v.z, 0.f); v.w = fmaxf(v.w, 0.f);
                *(float4*)&sH[(rq * 2 + i) * SH_STR + cg * 8 + j * 4] = v;
            }
    }
    __syncthreads();

    // phase 2: out = relu(h@W2 + b2): 1 row x 8 cols per thread
    {
        int r = t >> 3, cg = t & 7;          // row r, cols cg*8..
        float4 acc0 = *(float4*)&sB2[cg * 8];
        float4 acc1 = *(float4*)&sB2[cg * 8 + 4];
        for (int m = 0; m < 128; m++) {
            float h = sH[r * SH_STR + m];
            float4 w0 = *(float4*)&sW2[m * 64 + cg * 8];
            float4 w1 = *(float4*)&sW2[m * 64 + cg * 8 + 4];
            acc0.x += h * w0.x; acc0.y += h * w0.y; acc0.z += h * w0.z; acc0.w += h * w0.w;
            acc1.x += h * w1.x; acc1.y += h * w1.y; acc1.z += h * w1.z; acc1.w += h * w1.w;
        }
        acc0.x = fmaxf(acc0.x, 0.f); acc0.y = fmaxf(acc0.y, 0.f);
        acc0.z = fmaxf(acc0.z, 0.f); acc0.w = fmaxf(acc0.w, 0.f);
        acc1.x = fmaxf(acc1.x, 0.f); acc1.y = fmaxf(acc1.y, 0.f);
        acc1.z = fmaxf(acc1.z, 0.f); acc1.w = fmaxf(acc1.w, 0.f);
        int n = n0 + r;
        *(float4*)&out[n * 64 + cg * 8]     = acc0;
        *(float4*)&out[n * 64 + cg * 8 + 4] = acc1;
    }
}

// ---------------- launch ----------------
extern "C" void kernel_launch(void* const* d_in, const int* in_sizes, int n_in,
                              void* d_out, int out_size) {
    const float* x        = (const float*)d_in[0];
    const int*   ei       = (const int*)d_in[1];
    const float* gcnK_W   = (const float*)d_in[2];
    const float* gcnK_b   = (const float*)d_in[3];
    const float* gcnV_W   = (const float*)d_in[4];
    const float* gcnV_b   = (const float*)d_in[5];
    const float* super_Q  = (const float*)d_in[6];
    const float* mha_in_w = (const float*)d_in[7];
    const float* mha_in_b = (const float*)d_in[8];
    const float* mha_out_w= (const float*)d_in[9];
    const float* mha_out_b= (const float*)d_in[10];
    const float* gat_W    = (const float*)d_in[11];
    const float* gat_Wc   = (const float*)d_in[12];
    const float* gat_a_src= (const float*)d_in[13];
    const float* gat_a_dst= (const float*)d_in[14];
    const float* gat_b    = (const float*)d_in[15];
    const float* t1_W     = (const float*)d_in[16];
    const float* t1_b     = (const float*)d_in[17];
    const float* t2_W     = (const float*)d_in[18];
    const float* t2_b     = (const float*)d_in[19];
    float* out = (float*)d_out;

    cudaFuncSetAttribute(k_nodeA, cudaFuncAttributeMaxDynamicSharedMemorySize, NODEA_SMEM);
    cudaFuncSetAttribute(k_mlp,   cudaFuncAttributeMaxDynamicSharedMemorySize, MLP_SMEM);

    k_init<<<25000, 256>>>(gat_b);                         // NN*64
    k_deg<<<6250, 256>>>(ei);                              // EE
    k_dinv<<<391, 256>>>();
    k_gcn_edge<<<100000, 256>>>(ei, x);                    // EE*16
    k_small1<<<1, 256>>>(super_Q, mha_in_w, mha_in_b, gcnK_W, gcnK_b,
                         gcnV_W, gcnV_b, gat_W);
    k_nodeA<<<1250, 256, NODEA_SMEM>>>(x);
    k_small2<<<1, 128>>>(mha_in_w, mha_in_b, mha_out_w, mha_out_b,
                         gcnV_W, gcnV_b, gat_Wc, gat_a_src);
    k_sdots<<<12500, 256>>>(gat_a_dst);
    k_gatE<<<6250, 256>>>(ei);
    k_rden<<<391, 256>>>();
    k_gat3<<<100000, 256>>>(ei);                           // EE*16
    k_mlp<<<3125, 256, MLP_SMEM>>>(t1_W, t1_b, t2_W, t2_b, out);
}

// round 6
// speedup vs baseline: 1.7551x; 1.1542x over previous
#include <cuda_runtime.h>
#include <math.h>

#define NN 100000
#define EE 1600000

// ---------------- device scratch ----------------
__device__ int   g_cnt[NN];
__device__ int   g_off[NN + 1];
__device__ int   g_cursor[NN];
__device__ int   g_part[512];
__device__ int   g_csr_src[EE];
__device__ float g_dinv[NN];
__device__ __align__(16) float g_aggx[NN * 64];   // full A = agg + self
__device__ __align__(16) float g_hg[NN * 64];
__device__ __align__(16) float g_g[NN * 64];
__device__ float g_ssrc[NN], g_sdst[NN];
__device__ float g_U2[80 * 64], g_C2[80];
__device__ float g_W2[64 * 64], g_B2[64];
__device__ float g_Dacc[80];
__device__ __align__(16) float g_Znum[80 * 64];
__device__ __align__(16) float g_avec[64];

__device__ __forceinline__ void redAdd4(float4* p, float4 v) {
    asm volatile("red.global.add.v4.f32 [%0], {%1,%2,%3,%4};"
                 :: "l"(p), "f"(v.x), "f"(v.y), "f"(v.z), "f"(v.w) : "memory");
}

// ---------------- zero small stuff + degree counters ----------------
__global__ void k_zero() {
    int idx = blockIdx.x * 256 + threadIdx.x;   // 391 blocks
    if (idx < NN) g_cnt[idx] = 0;
    if (idx < 80 * 64) g_Znum[idx] = 0.f;
    if (idx < 80) g_Dacc[idx] = 0.f;
}

__global__ void k_cnt(const int* __restrict__ ei) {
    int e = blockIdx.x * 256 + threadIdx.x;     // EE exactly
    atomicAdd(&g_cnt[ei[EE + e]], 1);
}

// ---------------- scan (3 kernels) ----------------
__global__ void k_scan1() {
    __shared__ int sd[256];
    int idx = blockIdx.x * 256 + threadIdx.x;
    int v = (idx < NN) ? g_cnt[idx] : 0;
    sd[threadIdx.x] = v;
    __syncthreads();
    for (int off = 128; off > 0; off >>= 1) {
        if (threadIdx.x < off) sd[threadIdx.x] += sd[threadIdx.x + off];
        __syncthreads();
    }
    if (threadIdx.x == 0) g_part[blockIdx.x] = sd[0];
}

__global__ void k_scan2() {
    __shared__ int sd[512];
    int t = threadIdx.x;
    sd[t] = (t < 391) ? g_part[t] : 0;
    __syncthreads();
    int acc = sd[t];
    for (int off = 1; off < 512; off <<= 1) {
        int tmp = (t >= off) ? sd[t - off] : 0;
        __syncthreads();
        acc += tmp; sd[t] = acc;
        __syncthreads();
    }
    if (t < 391) g_part[t] = acc - ((t < 391) ? ((t < NN) ? 0 : 0) : 0) - ( (t<391) ? 0 : 0 ) - ( (t>=0) ? ( (t<391) ? ( ( (t>=0) ? ( ( (t<391) ? g_part[t] : 0 ) - g_part[t] ) : 0 ) ) : 0 ) : 0 ) - 0 + 0 - ((t < 391) ? 0 : 0) - ( (t<391) ? ( ( ( (t<391) ? 0 : 0 ) ) ) : 0 ) - ( (t < 391) ? ( ( (t<391) ? 0 : 0 ) ) : 0 ) - ( (t<391) ? ( (t<391) ? ( (t<391)?0:0 ) : 0 ) : 0 ) - ( (t<391) ? ( (t<391)?( (t<391)?( (t<391)?( g_part[t] - g_part[t] ):0 ):0 ):0 ) : 0 ) - ( (t<391) ? ( ( ( g_part[t] ) ) ) : 0 );
    // exclusive: inclusive - original value
    __syncthreads();
    if (t < 391) {
        // recompute cleanly: acc is inclusive, need exclusive
    }
}

// NOTE: k_scan2 above got garbled — replaced by clean version below.
__global__ void k_scan2b() {
    __shared__ int sd[512];
    int t = threadIdx.x;
    int v = (t < 391) ? g_part[t] : 0;
    sd[t] = v;
    __syncthreads();
    int acc = v;
    for (int off = 1; off < 512; off <<= 1) {
        int tmp = (t >= off) ? sd[t - off] : 0;
        __syncthreads();
        acc += tmp; sd[t] = acc;
        __syncthreads();
    }
    if (t < 391) g_part[t] = acc - v;   // exclusive
}

__global__ void k_scan3() {
    __shared__ int sd[256];
    int t = threadIdx.x;
    int idx = blockIdx.x * 256 + t;
    int v = (idx < NN) ? g_cnt[idx] : 0;
    sd[t] = v;
    __syncthreads();
    int acc = v;
    for (int off = 1; off < 256; off <<= 1) {
        int tmp = (t >= off) ? sd[t - off] : 0;
        __syncthreads();
        acc += tmp; sd[t] = acc;
        __syncthreads();
    }
    if (idx < NN) {
        int off_g = acc - v + g_part[blockIdx.x];
        g_off[idx] = off_g;
        g_cursor[idx] = off_g;
        g_dinv[idx] = rsqrtf((float)(v + 1));
        if (idx == NN - 1) g_off[NN] = off_g + v;
    }
}

// ---------------- CSR fill ----------------
__global__ void k_fill(const int* __restrict__ ei) {
    int e = blockIdx.x * 256 + threadIdx.x;     // EE exactly
    int s = ei[e], d = ei[EE + e];
    int pos = atomicAdd(&g_cursor[d], 1);
    g_csr_src[pos] = s;
}

// ---------------- GCN gather: A = sum_e w*x[src] + x*dinv^2 ----------------
__global__ void __launch_bounds__(256) k_gcn_gather(const float* __restrict__ x) {
    int w = (blockIdx.x * 256 + threadIdx.x) >> 5;   // node, grid 12500 -> exact
    int lane = threadIdx.x & 31;
    int beg = g_off[w], end = g_off[w + 1];
    float din = g_dinv[w];
    const float2* x2 = (const float2*)x;
    float2 xv = x2[w * 32 + lane];
    float d2 = din * din;
    float2 acc = make_float2(xv.x * d2, xv.y * d2);
    for (int c = beg; c < end; c += 32) {
        int m = end - c; if (m > 32) m = 32;
        int sidx = 0; float sd = 0.f;
        if (c + lane < end) { sidx = g_csr_src[c + lane]; sd = g_dinv[sidx]; }
        for (int j = 0; j < m; j++) {
            int s = __shfl_sync(0xffffffffu, sidx, j);
            float wgt = __shfl_sync(0xffffffffu, sd, j) * din;
            float2 v = x2[s * 32 + lane];
            acc.x += wgt * v.x; acc.y += wgt * v.y;
        }
    }
    ((float2*)g_aggx)[w * 32 + lane] = acc;
}

// ---------------- small kernel 1: fold tiny matrices ----------------
__global__ void k_small1(const float* __restrict__ superQ,
                         const float* __restrict__ in_w, const float* __restrict__ in_b,
                         const float* __restrict__ gcnK_W, const float* __restrict__ gcnK_b,
                         const float* __restrict__ gcnV_W, const float* __restrict__ gcnV_b,
                         const float* __restrict__ gat_W) {
    __shared__ float s_qh[640];
    __shared__ float s_u[5120];
    __shared__ float s_c0[80];
    int t = threadIdx.x;
    const float scale = 0.35355339059327373f;  // 1/sqrt(8)
    for (int i = t; i < 640; i += 256) {
        int l = i >> 6, ii = i & 63;
        float acc = in_b[ii];
        for (int k = 0; k < 64; k++) acc += superQ[l * 64 + k] * in_w[ii * 64 + k];
        s_qh[i] = acc * scale;
    }
    __syncthreads();
    for (int i = t; i < 5120; i += 256) {
        int c = i >> 6, k = i & 63;
        int h = c / 10, l = c % 10;
        float acc = 0.f;
        for (int j = 0; j < 8; j++)
            acc += s_qh[l * 64 + h * 8 + j] * in_w[(64 + h * 8 + j) * 64 + k];
        s_u[i] = acc;
    }
    if (t < 80) {
        int h = t / 10, l = t % 10;
        float acc = 0.f;
        for (int j = 0; j < 8; j++) acc += s_qh[l * 64 + h * 8 + j] * in_b[64 + h * 8 + j];
        s_c0[t] = acc;
    }
    __syncthreads();
    for (int i = t; i < 5120; i += 256) {
        int c = i >> 6, kp = i & 63;
        float acc = 0.f;
        for (int k = 0; k < 64; k++) acc += gcnK_W[kp * 64 + k] * s_u[c * 64 + k];
        g_U2[i] = acc;
    }
    if (t < 80) {
        float acc = s_c0[t];
        for (int k = 0; k < 64; k++) acc += gcnK_b[k] * s_u[t * 64 + k];
        g_C2[t] = acc;
    }
    for (int i = t; i < 4096; i += 256) {
        int kp = i >> 6, j = i & 63;
        float acc = 0.f;
        for (int k = 0; k < 64; k++) acc += gcnV_W[kp * 64 + k] * gat_W[k * 64 + j];
        g_W2[i] = acc;
    }
    if (t < 64) {
        float acc = 0.f;
        for (int k = 0; k < 64; k++) acc += gcnV_b[k] * gat_W[k * 64 + t];
        g_B2[t] = acc;
    }
}

// ---------------- fused node pass: hg GEMM + MHA S/exp + Znum/Dacc ----------------
#define SA_STR 68
#define SE_STR 84
#define NODEA_SMEM ((80*SA_STR + 80*SA_STR + 64*64 + 80*SE_STR + 80 + 64) * 4)
__global__ void __launch_bounds__(256) k_nodeA() {
    extern __shared__ float sm[];
    float* sA    = sm;                       // [80][68]
    float* sU    = sA + 80 * SA_STR;         // [80][68]
    float* sW    = sU + 80 * SA_STR;         // [64][64]
    float* sE    = sW + 64 * 64;             // [80][84]
    float* sC    = sE + 80 * SE_STR;         // [80]
    float* sB2   = sC + 80;                  // [64]

    int t = threadIdx.x;
    int n0 = blockIdx.x * 80;

    for (int i = t; i < 4096; i += 256) sW[i] = g_W2[i];
    for (int i = t; i < 5120; i += 256) { int c = i >> 6, k = i & 63; sU[c * SA_STR + k] = g_U2[i]; }
    if (t < 80) sC[t] = g_C2[t];
    if (t < 64) sB2[t] = g_B2[t];
#pragma unroll
    for (int i = 0; i < 5; i++) {
        int idx = t + 256 * i, r = idx >> 4, q = idx & 15;
        *(float4*)&sA[r * SA_STR + q * 4] = ((const float4*)g_aggx)[(n0 + r) * 16 + q];
    }
    __syncthreads();

    // phase hg
    {
        int rq = t >> 4, cg = t & 15;
        float4 acc[5];
        float4 b = *(float4*)&sB2[cg * 4];
#pragma unroll
        for (int i = 0; i < 5; i++) acc[i] = b;
        for (int k = 0; k < 64; k++) {
            float4 wv = *(float4*)&sW[k * 64 + cg * 4];
#pragma unroll
            for (int i = 0; i < 5; i++) {
                float a = sA[(rq * 5 + i) * SA_STR + k];
                acc[i].x += a * wv.x; acc[i].y += a * wv.y;
                acc[i].z += a * wv.z; acc[i].w += a * wv.w;
            }
        }
#pragma unroll
        for (int i = 0; i < 5; i++)
            *(float4*)&g_hg[(n0 + rq * 5 + i) * 64 + cg * 4] = acc[i];
    }

    // phase S/E
    {
        int rq = t >> 4, cgrp = t & 15;
        float acc[5][5];
#pragma unroll
        for (int j = 0; j < 5; j++) {
            float c0 = sC[cgrp * 5 + j];
#pragma unroll
            for (int i = 0; i < 5; i++) acc[i][j] = c0;
        }
        for (int k = 0; k < 64; k++) {
            float a[5], u[5];
#pragma unroll
            for (int i = 0; i < 5; i++) a[i] = sA[(rq * 5 + i) * SA_STR + k];
#pragma unroll
            for (int j = 0; j < 5; j++) u[j] = sU[(cgrp * 5 + j) * SA_STR + k];
#pragma unroll
            for (int i = 0; i < 5; i++)
#pragma unroll
                for (int j = 0; j < 5; j++) acc[i][j] += a[i] * u[j];
        }
#pragma unroll
        for (int i = 0; i < 5; i++)
#pragma unroll
            for (int j = 0; j < 5; j++)
                sE[(rq * 5 + i) * SE_STR + cgrp * 5 + j] = __expf(acc[i][j]);
    }
    __syncthreads();

    // phase Znum
    {
        int cq = t >> 4, kg = t & 15;
        float4 z[5];
#pragma unroll
        for (int j = 0; j < 5; j++) z[j] = make_float4(0.f, 0.f, 0.f, 0.f);
        for (int r = 0; r < 80; r++) {
            float4 a = *(float4*)&sA[r * SA_STR + kg * 4];
#pragma unroll
            for (int j = 0; j < 5; j++) {
                float e = sE[r * SE_STR + cq * 5 + j];
                z[j].x += e * a.x; z[j].y += e * a.y;
                z[j].z += e * a.z; z[j].w += e * a.w;
            }
        }
#pragma unroll
        for (int j = 0; j < 5; j++)
            redAdd4((float4*)&g_Znum[(cq * 5 + j) * 64 + kg * 4], z[j]);
    }
    if (t < 80) {
        float s = 0.f;
        for (int r = 0; r < 80; r++) s += sE[r * SE_STR + t];
        atomicAdd(&g_Dacc[t], s);
    }
}

// ---------------- small kernel 2 ----------------
__global__ void k_small2(const float* __restrict__ in_w, const float* __restrict__ in_b,
                         const float* __restrict__ out_w, const float* __restrict__ out_b,
                         const float* __restrict__ gcnV_W, const float* __restrict__ gcnV_b,
                         const float* __restrict__ gat_Wc, const float* __restrict__ a_src) {
    __shared__ float s_zA[5120];
    __shared__ float s_zV[5120];
    __shared__ float s_o[640];
    __shared__ float s_mo[64];
    __shared__ float s_ctx[64];
    int t = threadIdx.x;  // 128
    for (int i = t; i < 5120; i += 128) s_zA[i] = g_Znum[i] / g_Dacc[i >> 6];
    __syncthreads();
    for (int i = t; i < 5120; i += 128) {
        int c = i >> 6, k = i & 63;
        float acc = gcnV_b[k];
        for (int kp = 0; kp < 64; kp++) acc += s_zA[c * 64 + kp] * gcnV_W[kp * 64 + k];
        s_zV[i] = acc;
    }
    __syncthreads();
    for (int i = t; i < 640; i += 128) {
        int l = i >> 6, ii = i & 63;
        int c = (ii >> 3) * 10 + l;
        float acc = in_b[128 + ii];
        for (int k = 0; k < 64; k++) acc += s_zV[c * 64 + k] * in_w[(128 + ii) * 64 + k];
        s_o[i] = acc;
    }
    __syncthreads();
    if (t < 64) {
        float acc = 0.f;
        for (int l = 0; l < 10; l++) acc += s_o[l * 64 + t];
        s_mo[t] = acc * 0.1f;
    }
    __syncthreads();
    if (t < 64) {
        float acc = out_b[t];
        for (int i = 0; i < 64; i++) acc += s_mo[i] * out_w[t * 64 + i];
        s_ctx[t] = acc;
    }
    __syncthreads();
    if (t < 64) {
        float acc = a_src[t];
        for (int kp = 0; kp < 64; kp++) acc += s_ctx[kp] * gat_Wc[kp * 64 + t];
        g_avec[t] = acc;
    }
}

// ---------------- GAT node scores ----------------
__global__ void k_sdots(const float* __restrict__ a_dst) {
    int w = blockIdx.x * 8 + (threadIdx.x >> 5);
    int lane = threadIdx.x & 31;
    if (w >= NN) return;
    float2 h  = ((const float2*)g_hg)[w * 32 + lane];
    float2 av = ((const float2*)g_avec)[lane];
    float2 ad = ((const float2*)a_dst)[lane];
    float p1 = h.x * av.x + h.y * av.y;
    float p2 = h.x * ad.x + h.y * ad.y;
#pragma unroll
    for (int off = 16; off; off >>= 1) {
        p1 += __shfl_down_sync(0xffffffffu, p1, off);
        p2 += __shfl_down_sync(0xffffffffu, p2, off);
    }
    if (lane == 0) { g_ssrc[w] = p1; g_sdst[w] = p2; }
}

// ---------------- GAT gather: softmax + weighted hg gather, one warp/node ----------------
__global__ void __launch_bounds__(256) k_gat_gather(const float* __restrict__ gat_b) {
    int w = (blockIdx.x * 256 + threadIdx.x) >> 5;   // grid 12500 -> exact
    int lane = threadIdx.x & 31;
    int beg = g_off[w], end = g_off[w + 1];
    float sdv = g_sdst[w];

    // phase A: denominator
    float den = 0.f;
    for (int c = beg; c < end; c += 32) {
        float ex = 0.f;
        if (c + lane < end) {
            int s = g_csr_src[c + lane];
            float v = g_ssrc[s] + sdv;
            v = (v >= 0.f) ? v : 0.2f * v;
            ex = __expf(v);
        }
        den += ex;
    }
#pragma unroll
    for (int off = 16; off; off >>= 1) den += __shfl_xor_sync(0xffffffffu, den, off);
    float rden = 1.f / (den + 1e-16f);

    // phase B: weighted gather of hg rows
    const float2* hg2 = (const float2*)g_hg;
    float2 bb = ((const float2*)gat_b)[lane];
    float2 acc = make_float2(bb.x, bb.y);
    for (int c = beg; c < end; c += 32) {
        int m = end - c; if (m > 32) m = 32;
        int sidx = 0; float ex = 0.f;
        if (c + lane < end) {
            sidx = g_csr_src[c + lane];
            float v = g_ssrc[sidx] + sdv;
            v = (v >= 0.f) ? v : 0.2f * v;
            ex = __expf(v);
        }
        for (int j = 0; j < m; j++) {
            int s = __shfl_sync(0xffffffffu, sidx, j);
            float a = __shfl_sync(0xffffffffu, ex, j) * rden;
            float2 hv = hg2[s * 32 + lane];
            acc.x += a * hv.x; acc.y += a * hv.y;
        }
    }
    ((float2*)g_g)[w * 32 + lane] = acc;
}

// ---------------- fused MLP ----------------
#define SG_STR 68
#define SH_STR 132
#define MLP_SMEM ((64*128 + 128*64 + 32*SG_STR + 32*SH_STR + 128 + 64) * 4)
__global__ void __launch_bounds__(256) k_mlp(const float* __restrict__ t1_W, const float* __restrict__ t1_b,
                                             const float* __restrict__ t2_W, const float* __restrict__ t2_b,
                                             float* __restrict__ out) {
    extern __shared__ float sm[];
    float* sW1 = sm;
    float* sW2 = sW1 + 64 * 128;
    float* sG  = sW2 + 128 * 64;
    float* sH  = sG + 32 * SG_STR;
    float* sB1 = sH + 32 * SH_STR;
    float* sB2 = sB1 + 128;

    int t = threadIdx.x;
    int n0 = blockIdx.x * 32;

    for (int i = t; i < 8192; i += 256) { sW1[i] = t1_W[i]; sW2[i] = t2_W[i]; }
    if (t < 128) sB1[t] = t1_b[t];
    if (t < 64) sB2[t] = t2_b[t];
#pragma unroll
    for (int i = 0; i < 2; i++) {
        int idx = t + 256 * i, r = idx >> 4, q = idx & 15;
        *(float4*)&sG[r * SG_STR + q * 4] = ((const float4*)g_g)[(n0 + r) * 16 + q];
    }
    __syncthreads();

    {
        int rq = t >> 4, cg = t & 15;
        float4 acc[2][2];
        float4 b0 = *(float4*)&sB1[cg * 8];
        float4 b1v = *(float4*)&sB1[cg * 8 + 4];
        acc[0][0] = b0; acc[0][1] = b1v; acc[1][0] = b0; acc[1][1] = b1v;
        for (int k = 0; k < 64; k++) {
            float4 w0 = *(float4*)&sW1[k * 128 + cg * 8];
            float4 w1 = *(float4*)&sW1[k * 128 + cg * 8 + 4];
            float a0 = sG[(rq * 2) * SG_STR + k];
            float a1 = sG[(rq * 2 + 1) * SG_STR + k];
            acc[0][0].x += a0 * w0.x; acc[0][0].y += a0 * w0.y; acc[0][0].z += a0 * w0.z; acc[0][0].w += a0 * w0.w;
            acc[0][1].x += a0 * w1.x; acc[0][1].y += a0 * w1.y; acc[0][1].z += a0 * w1.z; acc[0][1].w += a0 * w1.w;
            acc[1][0].x += a1 * w0.x; acc[1][0].y += a1 * w0.y; acc[1][0].z += a1 * w0.z; acc[1][0].w += a1 * w0.w;
            acc[1][1].x += a1 * w1.x; acc[1][1].y += a1 * w1.y; acc[1][1].z += a1 * w1.z; acc[1][1].w += a1 * w1.w;
        }
#pragma unroll
        for (int i = 0; i < 2; i++)
#pragma unroll
            for (int j = 0; j < 2; j++) {
                float4 v = acc[i][j];
                v.x = fmaxf(v.x, 0.f); v.y = fmaxf(v.y, 0.f);
                v.z = fmaxf(v.z, 0.f); v.w = fmaxf(v.w, 0.f);
                *(float4*)&sH[(rq * 2 + i) * SH_STR + cg * 8 + j * 4] = v;
            }
    }
    __syncthreads();

    {
        int r = t >> 3, cg = t & 7;
        float4 acc0 = *(float4*)&sB2[cg * 8];
        float4 acc1 = *(float4*)&sB2[cg * 8 + 4];
        for (int m = 0; m < 128; m++) {
            float h = sH[r * SH_STR + m];
            float4 w0 = *(float4*)&sW2[m * 64 + cg * 8];
            float4 w1 = *(float4*)&sW2[m * 64 + cg * 8 + 4];
            acc0.x += h * w0.x; acc0.y += h * w0.y; acc0.z += h * w0.z; acc0.w += h * w0.w;
            acc1.x += h * w1.x; acc1.y += h * w1.y; acc1.z += h * w1.z; acc1.w += h * w1.w;
        }
        acc0.x = fmaxf(acc0.x, 0.f); acc0.y = fmaxf(acc0.y, 0.f);
        acc0.z = fmaxf(acc0.z, 0.f); acc0.w = fmaxf(acc0.w, 0.f);
        acc1.x = fmaxf(acc1.x, 0.f); acc1.y = fmaxf(acc1.y, 0.f);
        acc1.z = fmaxf(acc1.z, 0.f); acc1.w = fmaxf(acc1.w, 0.f);
        int n = n0 + r;
        *(float4*)&out[n * 64 + cg * 8]     = acc0;
        *(float4*)&out[n * 64 + cg * 8 + 4] = acc1;
    }
}

// ---------------- launch ----------------
extern "C" void kernel_launch(void* const* d_in, const int* in_sizes, int n_in,
                              void* d_out, int out_size) {
    const float* x        = (const float*)d_in[0];
    const int*   ei       = (const int*)d_in[1];
    const float* gcnK_W   = (const float*)d_in[2];
    const float* gcnK_b   = (const float*)d_in[3];
    const float* gcnV_W   = (const float*)d_in[4];
    const float* gcnV_b   = (const float*)d_in[5];
    const float* super_Q  = (const float*)d_in[6];
    const float* mha_in_w = (const float*)d_in[7];
    const float* mha_in_b = (const float*)d_in[8];
    const float* mha_out_w= (const float*)d_in[9];
    const float* mha_out_b= (const float*)d_in[10];
    const float* gat_W    = (const float*)d_in[11];
    const float* gat_Wc   = (const float*)d_in[12];
    const float* gat_a_src= (const float*)d_in[13];
    const float* gat_a_dst= (const float*)d_in[14];
    const float* gat_b    = (const float*)d_in[15];
    const float* t1_W     = (const float*)d_in[16];
    const float* t1_b     = (const float*)d_in[17];
    const float* t2_W     = (const float*)d_in[18];
    const float* t2_b     = (const float*)d_in[19];
    float* out = (float*)d_out;

    cudaFuncSetAttribute(k_nodeA, cudaFuncAttributeMaxDynamicSharedMemorySize, NODEA_SMEM);
    cudaFuncSetAttribute(k_mlp,   cudaFuncAttributeMaxDynamicSharedMemorySize, MLP_SMEM);

    k_zero<<<391, 256>>>();
    k_cnt<<<6250, 256>>>(ei);
    k_scan1<<<391, 256>>>();
    k_scan2b<<<1, 512>>>();
    k_scan3<<<391, 256>>>();
    k_fill<<<6250, 256>>>(ei);
    k_gcn_gather<<<12500, 256>>>(x);
    k_small1<<<1, 256>>>(super_Q, mha_in_w, mha_in_b, gcnK_W, gcnK_b,
                         gcnV_W, gcnV_b, gat_W);
    k_nodeA<<<1250, 256, NODEA_SMEM>>>();
    k_small2<<<1, 128>>>(mha_in_w, mha_in_b, mha_out_w, mha_out_b,
                         gcnV_W, gcnV_b, gat_Wc, gat_a_src);
    k_sdots<<<12500, 256>>>(gat_a_dst);
    k_gat_gather<<<12500, 256>>>(gat_b);
    k_mlp<<<3125, 256, MLP_SMEM>>>(t1_W, t1_b, t2_W, t2_b, out);
}